// round 1
// baseline (speedup 1.0000x reference)
#include <cuda_runtime.h>
#include <math.h>

#define Bn 4096
#define ROWS 4
#define GRID1 (Bn / ROWS)        // 1024 blocks
#define T1 256
#define CPT (Bn / T1)            // 16 columns per thread

// Scratch (written every launch, never accumulated -> no zeroing, deterministic)
__device__ float g_rs1[Bn];
__device__ float g_rs2[Bn];
__device__ float g_cp1[(size_t)GRID1 * Bn];   // 16 MB column partials of E
__device__ float g_cp2[(size_t)GRID1 * Bn];   // 16 MB column partials of E^2
__device__ float g_c1[Bn];
__device__ float g_c2[Bn];

// Pass 1: per 4-row stripe, compute row sums of E and E^2 (fully reduced) and
// per-block column partials. E = exp(L/t) = exp(2*v). One MUFU per element.
__global__ void __launch_bounds__(T1) k1_sums(const float* __restrict__ L) {
    const int t = threadIdx.x;
    const int r0 = blockIdx.x * ROWS;
    const int warp = t >> 5, lane = t & 31;

    float c1[CPT], c2[CPT];
#pragma unroll
    for (int k = 0; k < CPT; k++) { c1[k] = 0.0f; c2[k] = 0.0f; }

    __shared__ float s1[8][ROWS];
    __shared__ float s2[8][ROWS];

#pragma unroll
    for (int r = 0; r < ROWS; r++) {
        const float* __restrict__ row = L + (size_t)(r0 + r) * Bn;
        float rsum1 = 0.0f, rsum2 = 0.0f;
        float v[CPT];
#pragma unroll
        for (int k = 0; k < CPT; k++)           // front-batched loads (MLP=16)
            v[k] = row[t + k * T1];
#pragma unroll
        for (int k = 0; k < CPT; k++) {
            float e  = __expf(2.0f * v[k]);
            float e2 = e * e;
            rsum1 += e;  rsum2 += e2;
            c1[k] += e;  c2[k] += e2;
        }
#pragma unroll
        for (int o = 16; o > 0; o >>= 1) {
            rsum1 += __shfl_xor_sync(0xffffffffu, rsum1, o);
            rsum2 += __shfl_xor_sync(0xffffffffu, rsum2, o);
        }
        if (lane == 0) { s1[warp][r] = rsum1; s2[warp][r] = rsum2; }
    }
    __syncthreads();
    if (t < ROWS) {
        float a = 0.0f, b = 0.0f;
#pragma unroll
        for (int w = 0; w < 8; w++) { a += s1[w][t]; b += s2[w][t]; }
        g_rs1[r0 + t] = a;
        g_rs2[r0 + t] = b;
    }
    float* __restrict__ p1 = g_cp1 + (size_t)blockIdx.x * Bn;
    float* __restrict__ p2 = g_cp2 + (size_t)blockIdx.x * Bn;
#pragma unroll
    for (int k = 0; k < CPT; k++) {
        p1[t + k * T1] = c1[k];
        p2[t + k * T1] = c2[k];
    }
}

// Pass 2: reduce the 1024 column-partial stripes. 64 blocks x 256 threads:
// 64 columns per block, 4 p-stripes of 256 per thread, smem combine.
__global__ void __launch_bounds__(256) k2_colreduce() {
    const int tx = threadIdx.x & 63;          // column within block
    const int ty = threadIdx.x >> 6;          // p-stripe 0..3
    const int col = blockIdx.x * 64 + tx;
    float a = 0.0f, b = 0.0f;
    for (int p = ty * 256; p < (ty + 1) * 256; p++) {
        a += g_cp1[(size_t)p * Bn + col];
        b += g_cp2[(size_t)p * Bn + col];
    }
    __shared__ float sa[4][64];
    __shared__ float sb[4][64];
    sa[ty][tx] = a; sb[ty][tx] = b;
    __syncthreads();
    if (ty == 0) {
        float ra = sa[0][tx] + sa[1][tx] + sa[2][tx] + sa[3][tx];
        float rb = sb[0][tx] + sb[1][tx] + sb[2][tx] + sb[3][tx];
        g_c1[col] = ra;
        g_c2[col] = rb;
    }
}

// Pass 3: finalize per-row loss, mean over B rows (loss duplicates across halves).
__global__ void __launch_bounds__(1024) k3_finalize(const float* __restrict__ L,
                                                    float* __restrict__ out) {
    const int t = threadIdx.x;
    const float Nf   = 8190.0f;                 // 2B - 2
    const float minNg = 8190.0f * 0.13533528323661270f;  // N * exp(-1/t), t=0.5
    float acc = 0.0f;
    for (int i = t; i < Bn; i += 1024) {
        float v  = L[(size_t)i * Bn + i];
        float e  = __expf(2.0f * v);            // pos
        float e2 = e * e;
        float S1 = g_rs1[i] + g_c1[i] - 2.0f * e;
        float S2 = g_rs2[i] + g_c2[i] - 2.0f * e2;
        float rew = Nf * S2 / S1;
        float Ng  = (rew - 0.1f * Nf * e) * (1.0f / 0.9f);
        Ng = fmaxf(Ng, minNg);
        acc += logf((e + Ng + 1e-8f) / e);
    }
#pragma unroll
    for (int o = 16; o > 0; o >>= 1) acc += __shfl_xor_sync(0xffffffffu, acc, o);
    __shared__ float s[32];
    if ((t & 31) == 0) s[t >> 5] = acc;
    __syncthreads();
    if (t < 32) {
        float a = s[t];
#pragma unroll
        for (int o = 16; o > 0; o >>= 1) a += __shfl_xor_sync(0xffffffffu, a, o);
        if (t == 0) out[0] = a / (float)Bn;
    }
}

extern "C" void kernel_launch(void* const* d_in, const int* in_sizes, int n_in,
                              void* d_out, int out_size) {
    const float* L = (const float*)d_in[0];
    float* out = (float*)d_out;
    k1_sums<<<GRID1, T1>>>(L);
    k2_colreduce<<<Bn / 64, 256>>>();
    k3_finalize<<<1, 1024>>>(L, out);
}

// round 2
// speedup vs baseline: 1.8189x; 1.8189x over previous
#include <cuda_runtime.h>
#include <math.h>

#define Bn 4096
#define P1 296            // row stripes == grid of k1 (2 blocks/SM on 148 SMs)
#define T1 512

// Scratch (fully rewritten every launch -> deterministic, no zeroing)
__device__ float g_rs1[Bn];
__device__ float g_rs2[Bn];
__device__ float g_cp1[(size_t)P1 * Bn];   // 4.85 MB column partials of E
__device__ float g_cp2[(size_t)P1 * Bn];   // 4.85 MB column partials of E^2
__device__ float g_part[128];

// Pass 1: rows r = bid, bid+296, ... (13 or 14 rows/block). Row sums fully
// reduced; column sums kept in registers across all rows, written once.
__global__ void __launch_bounds__(T1) k1_sums(const float* __restrict__ L) {
    const int t = threadIdx.x;
    const int bid = blockIdx.x;
    const int warp = t >> 5, lane = t & 31;

    float c1[8], c2[8];
#pragma unroll
    for (int j = 0; j < 8; j++) { c1[j] = 0.0f; c2[j] = 0.0f; }

    __shared__ float s1[16][14];
    __shared__ float s2[16][14];

    int ri = 0;
    for (int r = bid; r < Bn; r += P1, ri++) {
        const float4* __restrict__ row4 = (const float4*)(L + (size_t)r * Bn);
        float4 a = __ldcs(row4 + t);          // cols 4t..4t+3
        float4 b = __ldcs(row4 + t + T1);     // cols 2048+4t..+3
        float x[8] = {a.x, a.y, a.z, a.w, b.x, b.y, b.z, b.w};
        float rs1 = 0.0f, rs2 = 0.0f;
#pragma unroll
        for (int j = 0; j < 8; j++) {
            float e  = __expf(2.0f * x[j]);
            float e2 = e * e;
            rs1 += e;  rs2 += e2;
            c1[j] += e; c2[j] += e2;
        }
#pragma unroll
        for (int o = 16; o > 0; o >>= 1) {
            rs1 += __shfl_xor_sync(0xffffffffu, rs1, o);
            rs2 += __shfl_xor_sync(0xffffffffu, rs2, o);
        }
        if (lane == 0) { s1[warp][ri] = rs1; s2[warp][ri] = rs2; }
    }
    const int nrows = ri;
    __syncthreads();
    if (t < nrows) {
        float a = 0.0f, b = 0.0f;
#pragma unroll
        for (int w = 0; w < 16; w++) { a += s1[w][t]; b += s2[w][t]; }
        g_rs1[bid + t * P1] = a;
        g_rs2[bid + t * P1] = b;
    }
    float4* __restrict__ p1 = (float4*)(g_cp1 + (size_t)bid * Bn);
    float4* __restrict__ p2 = (float4*)(g_cp2 + (size_t)bid * Bn);
    p1[t]      = make_float4(c1[0], c1[1], c1[2], c1[3]);
    p1[t + T1] = make_float4(c1[4], c1[5], c1[6], c1[7]);
    p2[t]      = make_float4(c2[0], c2[1], c2[2], c2[3]);
    p2[t + T1] = make_float4(c2[4], c2[5], c2[6], c2[7]);
}

// Pass 2: reduce 296 stripes (mostly L2-resident) + finalize per-row loss.
// 128 blocks x 256 thr: 32 cols/block, 8 stripe-groups of 37.
__global__ void __launch_bounds__(256) k2_finalize(const float* __restrict__ L) {
    const int tx = threadIdx.x & 31;
    const int g  = threadIdx.x >> 5;
    const int col = blockIdx.x * 32 + tx;

    float a = 0.0f, b = 0.0f;
    const int p0 = g * 37;
#pragma unroll 4
    for (int p = p0; p < p0 + 37; p++) {
        a += g_cp1[(size_t)p * Bn + col];
        b += g_cp2[(size_t)p * Bn + col];
    }
    __shared__ float sa[8][32];
    __shared__ float sb[8][32];
    sa[g][tx] = a;  sb[g][tx] = b;
    __syncthreads();

    if (threadIdx.x < 32) {
        float ra = 0.0f, rb = 0.0f;
#pragma unroll
        for (int w = 0; w < 8; w++) { ra += sa[w][tx]; rb += sb[w][tx]; }
        const int i = col;
        const float Nf    = 8190.0f;                         // 2B-2
        const float minNg = 8190.0f * 0.13533528323661270f;  // N*exp(-1/t)
        float d  = L[(size_t)i * Bn + i];
        float e  = __expf(2.0f * d);
        float e2 = e * e;
        float S1 = g_rs1[i] + ra - 2.0f * e;
        float S2 = g_rs2[i] + rb - 2.0f * e2;
        float Ng = (Nf * S2 / S1 - 0.1f * Nf * e) * (1.0f / 0.9f);
        Ng = fmaxf(Ng, minNg);
        float loss = logf((e + Ng + 1e-8f) / e);
#pragma unroll
        for (int o = 16; o > 0; o >>= 1)
            loss += __shfl_xor_sync(0xffffffffu, loss, o);
        if (tx == 0) g_part[blockIdx.x] = loss;
    }
}

// Pass 3: trivial 128-element reduce.
__global__ void __launch_bounds__(128) k3_out(float* __restrict__ out) {
    const int t = threadIdx.x;
    float v = g_part[t];
#pragma unroll
    for (int o = 16; o > 0; o >>= 1) v += __shfl_xor_sync(0xffffffffu, v, o);
    __shared__ float s[4];
    if ((t & 31) == 0) s[t >> 5] = v;
    __syncthreads();
    if (t == 0) out[0] = (s[0] + s[1] + s[2] + s[3]) / (float)Bn;
}

extern "C" void kernel_launch(void* const* d_in, const int* in_sizes, int n_in,
                              void* d_out, int out_size) {
    const float* L = (const float*)d_in[0];
    float* out = (float*)d_out;
    k1_sums<<<P1, T1>>>(L);
    k2_finalize<<<128, 256>>>(L);
    k3_out<<<1, 128>>>(out);
}

// round 3
// speedup vs baseline: 2.0550x; 1.1298x over previous
#include <cuda_runtime.h>

#define Bn 4096
#define P1 296            // 148 SMs x 2 blocks
#define T1 512

// Scratch (fully rewritten every launch; g_done returns to 0 every launch)
__device__ float g_rs1[Bn];
__device__ float g_rs2[Bn];
__device__ float g_cp1[(size_t)P1 * Bn];   // 4.85 MB col partials of E
__device__ float g_cp2[(size_t)P1 * Bn];   // 4.85 MB col partials of E^2
__device__ float g_part[128];
__device__ unsigned g_done;                // zero-init; reset by last block

__device__ __forceinline__ float ex2f(float x) {
    float r; asm("ex2.approx.ftz.f32 %0, %1;" : "=f"(r) : "f"(x)); return r;
}
#define SCALE 2.8853900817779268f          // (1/t)/ln2, t = 0.5

// Pass 1: rows r = bid + k*P1 (13 or 14 per block). Row pairs with scalar
// accumulators; shuffles only at pair end; 4 front-batched LDG.128 per iter.
__global__ void __launch_bounds__(T1, 2) k1_sums(const float* __restrict__ L) {
    const int t = threadIdx.x;
    const int bid = blockIdx.x;
    const int warp = t >> 5, lane = t & 31;
    const int R = (bid < 248) ? 14 : 13;   // 248*14 + 48*13 = 4096

    float c1[8], c2[8];
#pragma unroll
    for (int j = 0; j < 8; j++) { c1[j] = 0.f; c2[j] = 0.f; }

    __shared__ float s1[16][14];
    __shared__ float s2[16][14];

    int k = 0;
    for (; k + 2 <= R; k += 2) {
        const float4* __restrict__ rowA = (const float4*)(L + (size_t)(bid + k * P1) * Bn);
        const float4* __restrict__ rowB = (const float4*)(L + (size_t)(bid + (k + 1) * P1) * Bn);
        float4 a0 = __ldcs(rowA + t);
        float4 a1 = __ldcs(rowA + t + T1);
        float4 b0 = __ldcs(rowB + t);
        float4 b1 = __ldcs(rowB + t + T1);
        float xa[8] = {a0.x, a0.y, a0.z, a0.w, a1.x, a1.y, a1.z, a1.w};
        float xb[8] = {b0.x, b0.y, b0.z, b0.w, b1.x, b1.y, b1.z, b1.w};
        float ra1 = 0.f, ra2 = 0.f, rb1 = 0.f, rb2 = 0.f;
#pragma unroll
        for (int j = 0; j < 8; j++) {
            float ea = ex2f(xa[j] * SCALE);
            float eb = ex2f(xb[j] * SCALE);
            ra1 += ea;  rb1 += eb;
            c1[j] += ea + eb;
            ra2 = fmaf(ea, ea, ra2);
            rb2 = fmaf(eb, eb, rb2);
            c2[j] = fmaf(ea, ea, fmaf(eb, eb, c2[j]));
        }
#pragma unroll
        for (int o = 16; o > 0; o >>= 1) {
            ra1 += __shfl_xor_sync(~0u, ra1, o);
            ra2 += __shfl_xor_sync(~0u, ra2, o);
            rb1 += __shfl_xor_sync(~0u, rb1, o);
            rb2 += __shfl_xor_sync(~0u, rb2, o);
        }
        if (lane == 0) {
            s1[warp][k] = ra1;      s2[warp][k] = ra2;
            s1[warp][k + 1] = rb1;  s2[warp][k + 1] = rb2;
        }
    }
    if (k < R) {  // tail row (R odd)
        const float4* __restrict__ row = (const float4*)(L + (size_t)(bid + k * P1) * Bn);
        float4 a0 = __ldcs(row + t);
        float4 a1 = __ldcs(row + t + T1);
        float x[8] = {a0.x, a0.y, a0.z, a0.w, a1.x, a1.y, a1.z, a1.w};
        float ra1 = 0.f, ra2 = 0.f;
#pragma unroll
        for (int j = 0; j < 8; j++) {
            float e = ex2f(x[j] * SCALE);
            ra1 += e; c1[j] += e;
            ra2 = fmaf(e, e, ra2);
            c2[j] = fmaf(e, e, c2[j]);
        }
#pragma unroll
        for (int o = 16; o > 0; o >>= 1) {
            ra1 += __shfl_xor_sync(~0u, ra1, o);
            ra2 += __shfl_xor_sync(~0u, ra2, o);
        }
        if (lane == 0) { s1[warp][k] = ra1; s2[warp][k] = ra2; }
    }
    __syncthreads();
    if (t < R) {
        float a = 0.f, b = 0.f;
#pragma unroll
        for (int w = 0; w < 16; w++) { a += s1[w][t]; b += s2[w][t]; }
        g_rs1[bid + t * P1] = a;
        g_rs2[bid + t * P1] = b;
    }
    float4* __restrict__ p1 = (float4*)(g_cp1 + (size_t)bid * Bn);
    float4* __restrict__ p2 = (float4*)(g_cp2 + (size_t)bid * Bn);
    p1[t]      = make_float4(c1[0], c1[1], c1[2], c1[3]);
    p1[t + T1] = make_float4(c1[4], c1[5], c1[6], c1[7]);
    p2[t]      = make_float4(c2[0], c2[1], c2[2], c2[3]);
    p2[t + T1] = make_float4(c2[4], c2[5], c2[6], c2[7]);
}

// Pass 2: column reduce (L2-resident partials) + per-row loss + last-block
// final mean (deterministic: fixed-order sum computed by exactly one block).
__global__ void __launch_bounds__(256) k2_finalize(const float* __restrict__ L,
                                                   float* __restrict__ out) {
    const int tx = threadIdx.x & 31;
    const int g  = threadIdx.x >> 5;
    const int col = blockIdx.x * 32 + tx;

    float a = 0.0f, b = 0.0f;
    const int p0 = g * 37;                   // 8 * 37 = 296 stripes
#pragma unroll 4
    for (int p = p0; p < p0 + 37; p++) {
        a += g_cp1[(size_t)p * Bn + col];
        b += g_cp2[(size_t)p * Bn + col];
    }
    __shared__ float sa[8][32];
    __shared__ float sb[8][32];
    sa[g][tx] = a;  sb[g][tx] = b;
    __syncthreads();

    if (threadIdx.x < 32) {
        float ra = 0.0f, rb = 0.0f;
#pragma unroll
        for (int w = 0; w < 8; w++) { ra += sa[w][tx]; rb += sb[w][tx]; }
        const int i = col;
        const float Nf    = 8190.0f;                         // 2B-2
        const float minNg = 8190.0f * 0.13533528323661270f;  // N*exp(-1/t)
        float d  = L[(size_t)i * Bn + i];
        float e  = ex2f(d * SCALE);
        float e2 = e * e;
        float S1 = g_rs1[i] + ra - 2.0f * e;
        float S2 = g_rs2[i] + rb - 2.0f * e2;
        float Ng = (Nf * S2 / S1 - 0.1f * Nf * e) * (1.0f / 0.9f);
        Ng = fmaxf(Ng, minNg);
        float loss = logf((e + Ng + 1e-8f) / e);
#pragma unroll
        for (int o = 16; o > 0; o >>= 1)
            loss += __shfl_xor_sync(~0u, loss, o);
        if (tx == 0) g_part[blockIdx.x] = loss;
    }

    // completion counter: last arriving block does the final 128-way sum
    __shared__ bool last;
    if (threadIdx.x == 0) {
        __threadfence();                     // publish g_part before count
        unsigned n = atomicAdd(&g_done, 1u);
        last = (n == 127u);
    }
    __syncthreads();
    if (last) {
        __threadfence();
        if (threadIdx.x < 128) {
            float v = __ldcg(&g_part[threadIdx.x]);
#pragma unroll
            for (int o = 16; o > 0; o >>= 1)
                v += __shfl_xor_sync(~0u, v, o);
            __shared__ float s[4];
            if ((threadIdx.x & 31) == 0) s[threadIdx.x >> 5] = v;
            __syncthreads();
            if (threadIdx.x == 0) {
                out[0] = (s[0] + s[1] + s[2] + s[3]) / (float)Bn;
                atomicExch(&g_done, 0u);     // reset for next replay
            }
        }
    }
}

extern "C" void kernel_launch(void* const* d_in, const int* in_sizes, int n_in,
                              void* d_out, int out_size) {
    const float* L = (const float*)d_in[0];
    float* out = (float*)d_out;
    k1_sums<<<P1, T1>>>(L);
    k2_finalize<<<128, 256>>>(L, out);
}

// round 4
// speedup vs baseline: 2.2698x; 1.1046x over previous
#include <cuda_runtime.h>

#define Bn 4096
#define P1 296            // 148 SMs x 2 blocks
#define T1 512

// Scratch (fully rewritten every launch; g_done returns to 0 every launch)
__device__ float g_rs1[Bn];
__device__ float g_rs2[Bn];
__device__ float g_cp1[(size_t)P1 * Bn];   // 4.85 MB col partials of E
__device__ float g_cp2[(size_t)P1 * Bn];   // 4.85 MB col partials of E^2
__device__ float g_part[128];
__device__ unsigned g_done;                // zero-init; reset by last block

__device__ __forceinline__ float ex2f(float x) {
    float r; asm("ex2.approx.ftz.f32 %0, %1;" : "=f"(r) : "f"(x)); return r;
}
#define SCALE 2.8853900817779268f          // (1/t)/ln2, t = 0.5

// Pass 1 (unchanged — at LTS cap ~7.6TB/s): rows r = bid + k*P1.
__global__ void __launch_bounds__(T1, 2) k1_sums(const float* __restrict__ L) {
    const int t = threadIdx.x;
    const int bid = blockIdx.x;
    const int warp = t >> 5, lane = t & 31;
    const int R = (bid < 248) ? 14 : 13;   // 248*14 + 48*13 = 4096

    float c1[8], c2[8];
#pragma unroll
    for (int j = 0; j < 8; j++) { c1[j] = 0.f; c2[j] = 0.f; }

    __shared__ float s1[16][14];
    __shared__ float s2[16][14];

    int k = 0;
    for (; k + 2 <= R; k += 2) {
        const float4* __restrict__ rowA = (const float4*)(L + (size_t)(bid + k * P1) * Bn);
        const float4* __restrict__ rowB = (const float4*)(L + (size_t)(bid + (k + 1) * P1) * Bn);
        float4 a0 = __ldcs(rowA + t);
        float4 a1 = __ldcs(rowA + t + T1);
        float4 b0 = __ldcs(rowB + t);
        float4 b1 = __ldcs(rowB + t + T1);
        float xa[8] = {a0.x, a0.y, a0.z, a0.w, a1.x, a1.y, a1.z, a1.w};
        float xb[8] = {b0.x, b0.y, b0.z, b0.w, b1.x, b1.y, b1.z, b1.w};
        float ra1 = 0.f, ra2 = 0.f, rb1 = 0.f, rb2 = 0.f;
#pragma unroll
        for (int j = 0; j < 8; j++) {
            float ea = ex2f(xa[j] * SCALE);
            float eb = ex2f(xb[j] * SCALE);
            ra1 += ea;  rb1 += eb;
            c1[j] += ea + eb;
            ra2 = fmaf(ea, ea, ra2);
            rb2 = fmaf(eb, eb, rb2);
            c2[j] = fmaf(ea, ea, fmaf(eb, eb, c2[j]));
        }
#pragma unroll
        for (int o = 16; o > 0; o >>= 1) {
            ra1 += __shfl_xor_sync(~0u, ra1, o);
            ra2 += __shfl_xor_sync(~0u, ra2, o);
            rb1 += __shfl_xor_sync(~0u, rb1, o);
            rb2 += __shfl_xor_sync(~0u, rb2, o);
        }
        if (lane == 0) {
            s1[warp][k] = ra1;      s2[warp][k] = ra2;
            s1[warp][k + 1] = rb1;  s2[warp][k + 1] = rb2;
        }
    }
    if (k < R) {
        const float4* __restrict__ row = (const float4*)(L + (size_t)(bid + k * P1) * Bn);
        float4 a0 = __ldcs(row + t);
        float4 a1 = __ldcs(row + t + T1);
        float x[8] = {a0.x, a0.y, a0.z, a0.w, a1.x, a1.y, a1.z, a1.w};
        float ra1 = 0.f, ra2 = 0.f;
#pragma unroll
        for (int j = 0; j < 8; j++) {
            float e = ex2f(x[j] * SCALE);
            ra1 += e; c1[j] += e;
            ra2 = fmaf(e, e, ra2);
            c2[j] = fmaf(e, e, c2[j]);
        }
#pragma unroll
        for (int o = 16; o > 0; o >>= 1) {
            ra1 += __shfl_xor_sync(~0u, ra1, o);
            ra2 += __shfl_xor_sync(~0u, ra2, o);
        }
        if (lane == 0) { s1[warp][k] = ra1; s2[warp][k] = ra2; }
    }
    __syncthreads();
    if (t < R) {
        float a = 0.f, b = 0.f;
#pragma unroll
        for (int w = 0; w < 16; w++) { a += s1[w][t]; b += s2[w][t]; }
        g_rs1[bid + t * P1] = a;
        g_rs2[bid + t * P1] = b;
    }
    float4* __restrict__ p1 = (float4*)(g_cp1 + (size_t)bid * Bn);
    float4* __restrict__ p2 = (float4*)(g_cp2 + (size_t)bid * Bn);
    p1[t]      = make_float4(c1[0], c1[1], c1[2], c1[3]);
    p1[t + T1] = make_float4(c1[4], c1[5], c1[6], c1[7]);
    p2[t]      = make_float4(c2[0], c2[1], c2[2], c2[3]);
    p2[t + T1] = make_float4(c2[4], c2[5], c2[6], c2[7]);
}

// Pass 2: 128 blocks x 1024 threads. 32 cols/block x 32 stripe-groups
// (9-10 stripes each, coalesced 128B warp reads), smem tree, then per-row
// loss + last-block final mean (fixed-order sum by exactly one block).
__global__ void __launch_bounds__(1024) k2_finalize(const float* __restrict__ L,
                                                    float* __restrict__ out) {
    const int tx = threadIdx.x & 31;     // column within block
    const int g  = threadIdx.x >> 5;     // stripe group 0..31
    const int col = blockIdx.x * 32 + tx;

    float a = 0.0f, b = 0.0f;
#pragma unroll 10
    for (int p = g; p < P1; p += 32) {
        a += g_cp1[(size_t)p * Bn + col];
        b += g_cp2[(size_t)p * Bn + col];
    }
    __shared__ float sa[32][33];
    __shared__ float sb[32][33];
    sa[g][tx] = a;  sb[g][tx] = b;
    __syncthreads();

    if (threadIdx.x < 32) {
        float ra = 0.0f, rb = 0.0f;
#pragma unroll
        for (int w = 0; w < 32; w++) { ra += sa[w][tx]; rb += sb[w][tx]; }
        const int i = col;
        const float Nf    = 8190.0f;                         // 2B-2
        const float minNg = 8190.0f * 0.13533528323661270f;  // N*exp(-1/t)
        float d  = L[(size_t)i * Bn + i];
        float e  = ex2f(d * SCALE);
        float e2 = e * e;
        float S1 = g_rs1[i] + ra - 2.0f * e;
        float S2 = g_rs2[i] + rb - 2.0f * e2;
        float Ng = (Nf * S2 / S1 - 0.1f * Nf * e) * (1.0f / 0.9f);
        Ng = fmaxf(Ng, minNg);
        float loss = logf((e + Ng + 1e-8f) / e);
#pragma unroll
        for (int o = 16; o > 0; o >>= 1)
            loss += __shfl_xor_sync(~0u, loss, o);
        if (tx == 0) g_part[blockIdx.x] = loss;
    }

    // completion counter: last arriving block does the final 128-way sum
    __shared__ bool last;
    if (threadIdx.x == 0) {
        __threadfence();                     // publish g_part before count
        unsigned n = atomicAdd(&g_done, 1u);
        last = (n == 127u);
    }
    __syncthreads();
    if (last) {
        __threadfence();
        if (threadIdx.x < 128) {
            float v = __ldcg(&g_part[threadIdx.x]);
#pragma unroll
            for (int o = 16; o > 0; o >>= 1)
                v += __shfl_xor_sync(~0u, v, o);
            __shared__ float s[4];
            if ((threadIdx.x & 31) == 0) s[threadIdx.x >> 5] = v;
            __syncthreads();
            if (threadIdx.x == 0) {
                out[0] = (s[0] + s[1] + s[2] + s[3]) / (float)Bn;
                atomicExch(&g_done, 0u);     // reset for next replay
            }
        }
    }
}

extern "C" void kernel_launch(void* const* d_in, const int* in_sizes, int n_in,
                              void* d_out, int out_size) {
    const float* L = (const float*)d_in[0];
    float* out = (float*)d_out;
    k1_sums<<<P1, T1>>>(L);
    k2_finalize<<<128, 1024>>>(L, out);
}